// round 11
// baseline (speedup 1.0000x reference)
#include <cuda_runtime.h>
#include <cuda_fp16.h>
#include <stdint.h>

#define NPIX 32768            // B*H*W
#define QKVC 768

// Scratch (device globals; 16B-aligned)
__device__ __align__(16) __half g_qh[NPIX * QKVC];  // qkv fp16, [pixel][q|k|v]
__device__ __align__(16) __half g_bh[NPIX * 256];   // attn out fp16, [n][256]
__device__ __align__(16) __half g_wfh[1024 * 256];  // fused conv W fp16, [m][k]
__device__ __align__(16) __half g_wqh[QKVC * 256];  // qkv W fp16 (q pre-scaled), [m][k]
__device__ __align__(16) __half g_xh[256 * NPIX];   // x fp16, [k][n]
__device__ float g_bf[1024];

// ---------------------------------------------------------------------------
// helpers (non-arch-specific PTX only: cp.async / ldmatrix / mma.sync)
// ---------------------------------------------------------------------------
__device__ __forceinline__ uint32_t smem_u32(const void* p) {
    uint32_t a;
    asm("{ .reg .u64 t; cvta.to.shared.u64 t, %1; cvt.u32.u64 %0, t; }" : "=r"(a) : "l"(p));
    return a;
}
__device__ __forceinline__ void cp16(uint32_t d, const void* s) {
    asm volatile("cp.async.ca.shared.global [%0], [%1], 16;" :: "r"(d), "l"(s));
}
#define CP_COMMIT() asm volatile("cp.async.commit_group;")
#define CP_WAIT1()  asm volatile("cp.async.wait_group 1;")
#define CP_WAIT0()  asm volatile("cp.async.wait_group 0;")

__device__ __forceinline__ void ldm4(uint32_t* r, uint32_t a) {
    asm volatile("ldmatrix.sync.aligned.m8n8.x4.shared.b16 {%0,%1,%2,%3}, [%4];"
                 : "=r"(r[0]), "=r"(r[1]), "=r"(r[2]), "=r"(r[3]) : "r"(a));
}
__device__ __forceinline__ void ldm4t(uint32_t* r, uint32_t a) {
    asm volatile("ldmatrix.sync.aligned.m8n8.x4.trans.shared.b16 {%0,%1,%2,%3}, [%4];"
                 : "=r"(r[0]), "=r"(r[1]), "=r"(r[2]), "=r"(r[3]) : "r"(a));
}
__device__ __forceinline__ void mma_f16(float* d, const uint32_t* a, uint32_t b0, uint32_t b1) {
    asm volatile("mma.sync.aligned.m16n8k16.row.col.f32.f16.f16.f32 "
                 "{%0,%1,%2,%3}, {%4,%5,%6,%7}, {%8,%9}, {%0,%1,%2,%3};"
                 : "+f"(d[0]), "+f"(d[1]), "+f"(d[2]), "+f"(d[3])
                 : "r"(a[0]), "r"(a[1]), "r"(a[2]), "r"(a[3]), "r"(b0), "r"(b1));
}
__device__ __forceinline__ uint32_t packh(__half a, __half b) {
    return (uint32_t)__half_as_ushort(a) | ((uint32_t)__half_as_ushort(b) << 16);
}

// ---------------------------------------------------------------------------
// K0: fuse wo into conv: Wf = wc @ wo (fp16), bf = wc@bo + bc
// ---------------------------------------------------------------------------
__global__ __launch_bounds__(256) void k_fuse(const float* __restrict__ wo,
                                              const float* __restrict__ bo,
                                              const float* __restrict__ wc,
                                              const float* __restrict__ bc)
{
    int ob = blockIdx.x * 4;
    int i  = threadIdx.x;
    float a0 = 0.f, a1 = 0.f, a2 = 0.f, a3 = 0.f;
    for (int cc = 0; cc < 256; cc++) {
        float w = wo[cc * 256 + i];
        a0 += wc[(ob + 0) * 256 + cc] * w;
        a1 += wc[(ob + 1) * 256 + cc] * w;
        a2 += wc[(ob + 2) * 256 + cc] * w;
        a3 += wc[(ob + 3) * 256 + cc] * w;
    }
    float vals[4] = {a0, a1, a2, a3};
#pragma unroll
    for (int j = 0; j < 4; j++)
        g_wfh[(size_t)(ob + j) * 256 + i] = __float2half_rn(vals[j]);
    if (i < 4) {
        int o = ob + i;
        float s = 0.f;
        for (int c2 = 0; c2 < 256; c2++) s += wc[o * 256 + c2] * bo[c2];
        g_bf[o] = s + bc[o];
    }
}

// ---------------------------------------------------------------------------
// K0b: wq (pre-scaled by 0.125) / wkv -> fp16 row-major [768][256]
// ---------------------------------------------------------------------------
__global__ __launch_bounds__(256) void k_splitw(const float* __restrict__ wq,
                                                const float* __restrict__ wkv)
{
    int i = blockIdx.x * 256 + threadIdx.x;
    int m = i >> 8, c = i & 255;
    float v = (m < 256) ? wq[m * 256 + c] * 0.125f : wkv[(m - 256) * 256 + c];
    g_wqh[i] = __float2half_rn(v);
}

// ---------------------------------------------------------------------------
// K0c: x -> fp16 [k=channel][n=b*4096+p]
// ---------------------------------------------------------------------------
__global__ __launch_bounds__(256) void k_splitx(const float* __restrict__ x)
{
    size_t i = (size_t)(blockIdx.x * 256 + threadIdx.x) * 4;
    float4 v = *(const float4*)(x + i);
    size_t o = (size_t)((i >> 12) & 255) * NPIX + ((i >> 20) << 12) + (i & 4095);
    *(uint2*)&g_xh[o] = make_uint2(packh(__float2half_rn(v.x), __float2half_rn(v.y)),
                                   packh(__float2half_rn(v.z), __float2half_rn(v.w)));
}

// ---------------------------------------------------------------------------
// K1: QKV projection. C[768,32768] = W @ X, fp16. B panel (full K, 128 n)
// resident in smem; CTA loops over 3 m-tiles. Grid (256 n-blocks, 2 m-groups).
// smem: B [256 k][136] = 69632 | A ring 3x10240 (tb overlays ring in epilogue)
// ---------------------------------------------------------------------------
#define QKB_BYTES 69632
#define QKA_BUF   10240
#define QK_SMEM   (QKB_BYTES + 3 * QKA_BUF)   // 100352

__global__ void __launch_bounds__(256, 2) k_qkv_tc()
{
    extern __shared__ char qsm[];
    uint32_t base = smem_u32(qsm);
    int tid = threadIdx.x, lane = tid & 31, wrp = tid >> 5;
    int wm = wrp >> 1, wn = wrp & 1;
    int n0 = blockIdx.x << 7;
    int mtg = blockIdx.y * 3;

    // ---- load full B panel: 256 k-rows x 128 n, stride 136 halfs ----
    {
        int chunk = tid & 15, r0 = tid >> 4;
#pragma unroll
        for (int p = 0; p < 16; p++) {
            int row = p * 16 + r0;
            cp16(base + ((row * 136 + chunk * 8) << 1),
                 g_xh + (size_t)row * NPIX + n0 + chunk * 8);
        }
        CP_COMMIT();
    }
    int ar = tid >> 1, ac = (tid & 1) << 4;

    for (int mi = 0; mi < 3; mi++) {
        int m0 = (mtg + mi) << 7;
        float acc[2][8][4];
#pragma unroll
        for (int a = 0; a < 2; a++)
#pragma unroll
            for (int b = 0; b < 8; b++)
#pragma unroll
                for (int c = 0; c < 4; c++) acc[a][b][c] = 0.f;

        auto issueA = [&](int s, int buf) {
            const __half* A = g_wqh + (size_t)(m0 + ar) * 256 + (s << 5) + ac;
            uint32_t da = base + QKB_BYTES + buf * QKA_BUF + ((ar * 40 + ac) << 1);
            cp16(da, A); cp16(da + 16, A + 8);
        };
        issueA(0, 0); CP_COMMIT();
        issueA(1, 1); CP_COMMIT();
        for (int s = 0; s < 8; s++) {
            if (s < 7) CP_WAIT1(); else CP_WAIT0();
            __syncthreads();
            if (s + 2 < 8) { issueA(s + 2, (s + 2) % 3); CP_COMMIT(); }
            uint32_t ab = base + QKB_BYTES + (s % 3) * QKA_BUF;
#pragma unroll
            for (int kh = 0; kh < 32; kh += 16) {
                uint32_t ah[2][4];
#pragma unroll
                for (int mf = 0; mf < 2; mf++)
                    ldm4(ah[mf], ab + (((wm * 32 + mf * 16 + (lane & 15)) * 40
                                       + kh + ((lane >> 4) << 3)) << 1));
                int krow = (s << 5) + kh + ((lane >> 3) & 1) * 8 + (lane & 7);
#pragma unroll
                for (int nb = 0; nb < 4; nb++) {
                    uint32_t bh4[4];
                    ldm4t(bh4, base + ((krow * 136 + wn * 64 + nb * 16
                                        + ((lane >> 4) << 3)) << 1));
#pragma unroll
                    for (int mf = 0; mf < 2; mf++) {
                        mma_f16(acc[mf][nb * 2],     ah[mf], bh4[0], bh4[1]);
                        mma_f16(acc[mf][nb * 2 + 1], ah[mf], bh4[2], bh4[3]);
                    }
                }
            }
        }
        __syncthreads();

        // epilogue: transpose per 32-row m-quarter via smem (overlays A ring)
        float* tb = (float*)(qsm + QKB_BYTES);
        int g = lane >> 2, q = lane & 3;
#pragma unroll
        for (int mq = 0; mq < 4; mq++) {
            if (wm == mq) {
#pragma unroll
                for (int mf = 0; mf < 2; mf++)
#pragma unroll
                    for (int nf = 0; nf < 8; nf++) {
                        int nl = wn * 64 + nf * 8 + q * 2;
                        int ml = mf * 16 + g;
                        tb[nl * 33 + ml]            = acc[mf][nf][0];
                        tb[(nl + 1) * 33 + ml]      = acc[mf][nf][1];
                        tb[nl * 33 + ml + 8]        = acc[mf][nf][2];
                        tb[(nl + 1) * 33 + ml + 8]  = acc[mf][nf][3];
                    }
            }
            __syncthreads();
            int nl = tid >> 1, half2 = tid & 1;
            const float* src = tb + nl * 33 + half2 * 16;
            size_t dst = (size_t)(n0 + nl) * QKVC + m0 + mq * 32 + half2 * 16;
            unsigned short hs[16];
#pragma unroll
            for (int u = 0; u < 16; u++)
                hs[u] = __half_as_ushort(__float2half_rn(src[u]));
            *(uint4*)&g_qh[dst]     = *(uint4*)&hs[0];
            *(uint4*)&g_qh[dst + 8] = *(uint4*)&hs[8];
            __syncthreads();
        }
    }
}

// ---------------------------------------------------------------------------
// K2: tensor-core halo attention (rel logits via MMA; dual-buffer reduction).
// ---------------------------------------------------------------------------
#define AT_SQ    0
#define AT_SK    9216
#define AT_RELH  46080
#define AT_RELW  50688
#define AT_GW    55296
#define AT_GH    63744
#define AT_RMX   72192
#define AT_RSUM  72704
#define AT_RED2  73216
#define AT_SMEM  90624

__global__ void __launch_bounds__(256, 2) k_attn_tc(const float* __restrict__ relh,
                                                    const float* __restrict__ relw)
{
    extern __shared__ char smc[];
    uint32_t sb = smem_u32(smc);
    int t = threadIdx.x, lane = t & 31, wid = t >> 5;
    int wm = wid >> 1, wn = wid & 1;
    int nbk = blockIdx.x, hh = blockIdx.y;
    int bi = nbk >> 6, tbw = nbk & 63;
    int bh = tbw >> 3, bw = tbw & 7;
    int hco = hh * 64;

    uint32_t qB = sb + AT_SQ;
    uint32_t kB = sb + AT_SK;

    {
        int chunk = t & 7, rr = t >> 3;
        {
            int row = rr;
            int qx = row >> 3, qy = row & 7;
            size_t pix = (size_t)(bi * 4096 + (bh * 8 + qx) * 64 + bw * 8 + qy) * QKVC + hco;
            ((uint4*)(smc + AT_SQ))[row * 9 + chunk] = *(const uint4*)(g_qh + pix + chunk * 8);
            row = rr + 32;
            qx = row >> 3; qy = row & 7;
            pix = (size_t)(bi * 4096 + (bh * 8 + qx) * 64 + bw * 8 + qy) * QKVC + hco;
            ((uint4*)(smc + AT_SQ))[row * 9 + chunk] = *(const uint4*)(g_qh + pix + chunk * 8);
        }
#pragma unroll
        for (int p = 0; p < 8; p++) {
            int row = p * 32 + rr;
            int ki = row >> 4, kj = row & 15;
            int gh = bh * 8 - 4 + ki, gw = bw * 8 - 4 + kj;
            bool valid = ((unsigned)gh < 64u) && ((unsigned)gw < 64u);
            size_t pix = (size_t)(valid ? bi * 4096 + gh * 64 + gw : bi * 4096) * QKVC
                       + 256 + hco + chunk * 8;
            uint4 z = make_uint4(0, 0, 0, 0);
            ((uint4*)(smc + AT_SK))[row * 9 + chunk] = valid ? *(const uint4*)(g_qh + pix) : z;
        }
        for (int idx = t; idx < 1152; idx += 256) {
            ((uint32_t*)(smc + AT_RELH))[idx] = 0;
            ((uint32_t*)(smc + AT_RELW))[idx] = 0;
        }
        __syncthreads();
        for (int idx = t; idx < 1984; idx += 256) {
            int r = idx >> 6, dd = idx & 63;
            ((__half*)(smc + AT_RELH))[r * 72 + dd] = __float2half_rn(relh[idx]);
            ((__half*)(smc + AT_RELW))[r * 72 + dd] = __float2half_rn(relw[idx]);
        }
    }
    __syncthreads();

    // ---- rel logits via MMA: wn==0 -> Gw, wn==1 -> Gh ----
    {
        float racc[4][4];
#pragma unroll
        for (int a = 0; a < 4; a++)
#pragma unroll
            for (int b = 0; b < 4; b++) racc[a][b] = 0.f;
        uint32_t relB = sb + (wn ? AT_RELH : AT_RELW);
#pragma unroll
        for (int kt = 0; kt < 4; kt++) {
            uint32_t ah[4];
            ldm4(ah, qB + (((wm * 16 + (lane & 15)) * 72 + kt * 16 + ((lane >> 4) << 3)) << 1));
#pragma unroll
            for (int nb = 0; nb < 2; nb++) {
                uint32_t bh4[4];
                ldm4(bh4, relB + (((nb * 16 + ((lane >> 4) << 3) + (lane & 7)) * 72
                                   + kt * 16 + (((lane >> 3) & 1) << 3)) << 1));
                mma_f16(racc[nb * 2],     ah, bh4[0], bh4[1]);
                mma_f16(racc[nb * 2 + 1], ah, bh4[2], bh4[3]);
            }
        }
        float* G = (float*)(smc + (wn ? AT_GH : AT_GW));
        int g2 = lane >> 2, tt = lane & 3;
#pragma unroll
        for (int j = 0; j < 4; j++)
#pragma unroll
            for (int e = 0; e < 4; e++) {
                int row = wm * 16 + g2 + ((e >= 2) ? 8 : 0);
                int col = j * 8 + 2 * tt + (e & 1);
                G[row * 33 + col] = racc[j][e];
            }
    }

    // ---- QK^T ----
    float s[16][4];
#pragma unroll
    for (int a = 0; a < 16; a++)
#pragma unroll
        for (int b = 0; b < 4; b++) s[a][b] = 0.f;
#pragma unroll
    for (int kt = 0; kt < 4; kt++) {
        uint32_t ah[4];
        ldm4(ah, qB + (((wm * 16 + (lane & 15)) * 72 + kt * 16 + ((lane >> 4) << 3)) << 1));
#pragma unroll
        for (int nb = 0; nb < 8; nb++) {
            uint32_t boff = (((wn * 128 + nb * 16 + ((lane >> 4) << 3) + (lane & 7)) * 72
                             + kt * 16 + (((lane >> 3) & 1) << 3)) << 1);
            uint32_t bh4[4];
            ldm4(bh4, kB + boff);
            mma_f16(s[nb * 2],     ah, bh4[0], bh4[1]);
            mma_f16(s[nb * 2 + 1], ah, bh4[2], bh4[3]);
        }
    }
    __syncthreads();

    // ---- prefetch V into K buffer ----
    {
        int chunk = t & 7, rr = t >> 3;
#pragma unroll
        for (int p = 0; p < 8; p++) {
            int row = p * 32 + rr;
            int ki = row >> 4, kj = row & 15;
            int gh = bh * 8 - 4 + ki, gw = bw * 8 - 4 + kj;
            bool valid = ((unsigned)gh < 64u) && ((unsigned)gw < 64u);
            size_t pix = (size_t)(valid ? bi * 4096 + gh * 64 + gw : bi * 4096) * QKVC
                       + 512 + hco + chunk * 8;
            cp16(kB + ((uint32_t)(row * 9 + chunk) << 4), g_qh + pix);
        }
        CP_COMMIT();
    }

    // ---- fixup: rel logits + mask ----
    {
        const float* Gw = (const float*)(smc + AT_GW);
        const float* Gh = (const float*)(smc + AT_GH);
        int g = lane >> 2, tt = lane & 3;
#pragma unroll
        for (int nt = 0; nt < 16; nt++) {
            int jbase = wn * 128 + nt * 8 + 2 * tt;
#pragma unroll
            for (int e = 0; e < 4; e++) {
                int row = wm * 16 + g + ((e >= 2) ? 8 : 0);
                int jj = jbase + (e & 1);
                int ki = jj >> 4, kj = jj & 15;
                int gh = bh * 8 - 4 + ki, gw = bw * 8 - 4 + kj;
                if (((unsigned)gh >= 64u) || ((unsigned)gw >= 64u))
                    s[nt][e] = -3.0e38f;
                else
                    s[nt][e] += Gw[row * 33 + kj - (row & 7) + 15]
                              + Gh[row * 33 + ki - (row >> 3) + 15];
            }
        }
    }

    float* rmx  = (float*)(smc + AT_RMX);
    float* rsum = (float*)(smc + AT_RSUM);
    int gg = lane >> 2;
    int rA = wm * 16 + gg, rB = rA + 8;
    {
        float mA = -3.4e38f, mB = -3.4e38f;
#pragma unroll
        for (int nt = 0; nt < 16; nt++) {
            mA = fmaxf(mA, fmaxf(s[nt][0], s[nt][1]));
            mB = fmaxf(mB, fmaxf(s[nt][2], s[nt][3]));
        }
        mA = fmaxf(mA, __shfl_xor_sync(0xffffffffu, mA, 1));
        mA = fmaxf(mA, __shfl_xor_sync(0xffffffffu, mA, 2));
        mB = fmaxf(mB, __shfl_xor_sync(0xffffffffu, mB, 1));
        mB = fmaxf(mB, __shfl_xor_sync(0xffffffffu, mB, 2));
        if ((lane & 3) == 0) { rmx[wn * 64 + rA] = mA; rmx[wn * 64 + rB] = mB; }
    }
    __syncthreads();
    {
        float mA = fmaxf(rmx[rA], rmx[64 + rA]);
        float mB = fmaxf(rmx[rB], rmx[64 + rB]);
        float sA = 0.f, sB = 0.f;
#pragma unroll
        for (int nt = 0; nt < 16; nt++) {
            s[nt][0] = __expf(s[nt][0] - mA); sA += s[nt][0];
            s[nt][1] = __expf(s[nt][1] - mA); sA += s[nt][1];
            s[nt][2] = __expf(s[nt][2] - mB); sB += s[nt][2];
            s[nt][3] = __expf(s[nt][3] - mB); sB += s[nt][3];
        }
        sA += __shfl_xor_sync(0xffffffffu, sA, 1);
        sA += __shfl_xor_sync(0xffffffffu, sA, 2);
        sB += __shfl_xor_sync(0xffffffffu, sB, 1);
        sB += __shfl_xor_sync(0xffffffffu, sB, 2);
        if ((lane & 3) == 0) { rsum[wn * 64 + rA] = sA; rsum[wn * 64 + rB] = sB; }
    }
    __syncthreads();
    {
        float invA = 1.0f / (rsum[rA] + rsum[64 + rA]);
        float invB = 1.0f / (rsum[rB] + rsum[64 + rB]);
#pragma unroll
        for (int nt = 0; nt < 16; nt++) {
            __half h0 = __float2half_rn(s[nt][0] * invA);
            __half h1 = __float2half_rn(s[nt][1] * invA);
            __half h2 = __float2half_rn(s[nt][2] * invB);
            __half h3 = __float2half_rn(s[nt][3] * invB);
            s[nt][0] = __uint_as_float(packh(h0, h1));
            s[nt][1] = __uint_as_float(packh(h2, h3));
        }
    }
    CP_WAIT0();
    __syncthreads();

    // ---- AV ----
    float avc[8][4];
#pragma unroll
    for (int a = 0; a < 8; a++)
#pragma unroll
        for (int b = 0; b < 4; b++) avc[a][b] = 0.f;
#pragma unroll
    for (int kt2 = 0; kt2 < 8; kt2++) {
        uint32_t pa[4] = { __float_as_uint(s[2 * kt2][0]), __float_as_uint(s[2 * kt2][1]),
                           __float_as_uint(s[2 * kt2 + 1][0]), __float_as_uint(s[2 * kt2 + 1][1]) };
#pragma unroll
        for (int nb = 0; nb < 4; nb++) {
            uint32_t off = (((wn * 128 + kt2 * 16 + ((lane >> 3) & 1) * 8 + (lane & 7)) * 72
                            + nb * 16 + ((lane >> 4) << 3)) << 1);
            uint32_t vh4[4];
            ldm4t(vh4, kB + off);
            mma_f16(avc[nb * 2],     pa, vh4[0], vh4[1]);
            mma_f16(avc[nb * 2 + 1], pa, vh4[2], vh4[3]);
        }
    }

    // dual-buffer reduction: wn==0 -> Red1 (overlays sK), wn==1 -> Red2
    float* Red1 = (float*)(smc + AT_SK);
    float* Red2 = (float*)(smc + AT_RED2);
    __syncthreads();
    {
        float* Rd = wn ? Red2 : Red1;
#pragma unroll
        for (int nf = 0; nf < 8; nf++)
#pragma unroll
            for (int e = 0; e < 4; e++) {
                int row = wm * 16 + gg + ((e >= 2) ? 8 : 0);
                int col = nf * 8 + 2 * (lane & 3) + (e & 1);
                Rd[row * 68 + col] = avc[nf][e];
            }
    }
    __syncthreads();

    {
        int qi = t >> 2, c0 = (t & 3) * 16;
        int qx = qi >> 3, qy = qi & 7;
        size_t base = (size_t)(bi * 4096 + (bh * 8 + qx) * 64 + bw * 8 + qy) * 256 + hco + c0;
        unsigned short hs[16];
#pragma unroll
        for (int u = 0; u < 16; u++)
            hs[u] = __half_as_ushort(__float2half_rn(Red1[qi * 68 + c0 + u]
                                                   + Red2[qi * 68 + c0 + u]));
        *(uint4*)&g_bh[base]     = *(uint4*)&hs[0];
        *(uint4*)&g_bh[base + 8] = *(uint4*)&hs[8];
    }
}

// ---------------------------------------------------------------------------
// K3: output GEMM + PixelShuffle. B panel resident; CTA loops over 4 m-tiles.
// Grid (256 n-blocks, 2 m-groups). Next m-tile's A stages issued before the
// (register-only) epilogue.
// smem: B [128 n][264] = 67584 | A ring 3x10240
// ---------------------------------------------------------------------------
#define KOB_BYTES 67584
#define KOA_BUF   10240
#define KO_SMEM   (KOB_BYTES + 3 * KOA_BUF)   // 98304

__global__ void __launch_bounds__(256, 2) k_out_tc(float* __restrict__ out)
{
    extern __shared__ char osm[];
    uint32_t base = smem_u32(osm);
    int tid = threadIdx.x, lane = tid & 31, wrp = tid >> 5;
    int wm = wrp >> 1, wn = wrp & 1;
    int n0 = blockIdx.x << 7;
    int mtg = blockIdx.y * 4;

    // ---- load full B panel: 128 pixels x 256 k, stride 264 halfs ----
    {
        int chunk = tid & 31, r0 = tid >> 5;
#pragma unroll
        for (int p = 0; p < 16; p++) {
            int row = p * 8 + r0;
            cp16(base + ((row * 264 + chunk * 8) << 1),
                 g_bh + (size_t)(n0 + row) * 256 + chunk * 8);
        }
        CP_COMMIT();
    }
    int ar = tid >> 1, ac = (tid & 1) << 4;
    int g = lane >> 2, q = lane & 3;
    int h0 = (n0 & 4095) >> 6, bimg = n0 >> 12;
    int hrow = h0 + wn;

    auto issueA = [&](int m0, int s, int buf) {
        const __half* A = g_wfh + (size_t)(m0 + ar) * 256 + (s << 5) + ac;
        uint32_t da = base + KOB_BYTES + buf * KOA_BUF + ((ar * 40 + ac) << 1);
        cp16(da, A); cp16(da + 16, A + 8);
    };

    issueA(mtg << 7, 0, 0); CP_COMMIT();
    issueA(mtg << 7, 1, 1); CP_COMMIT();

    for (int mi = 0; mi < 4; mi++) {
        int m0 = (mtg + mi) << 7;
        float acc[2][8][4];
#pragma unroll
        for (int a = 0; a < 2; a++)
#pragma unroll
            for (int b = 0; b < 8; b++)
#pragma unroll
                for (int c = 0; c < 4; c++) acc[a][b][c] = 0.f;

        for (int s = 0; s < 8; s++) {
            if (s < 7) CP_WAIT1(); else CP_WAIT0();
            __syncthreads();
            if (s + 2 < 8) { issueA(m0, s + 2, (s + 2) % 3); CP_COMMIT(); }
            uint32_t ab = base + KOB_BYTES + (s % 3) * KOA_BUF;
#pragma unroll
            for (int kh = 0; kh < 32; kh += 16) {
                uint32_t ah[2][4];
#pragma unroll
                for (int mf = 0; mf < 2; mf++)
                    ldm4(ah[mf], ab + (((wm * 32 + mf * 16 + (lane & 15)) * 40
                                       + kh + ((lane >> 4) << 3)) << 1));
                int kcol = (s << 5) + kh + (((lane >> 3) & 1) << 3);
#pragma unroll
                for (int nb = 0; nb < 4; nb++) {
                    int nrow = wn * 64 + nb * 16 + ((lane >> 4) << 3) + (lane & 7);
                    uint32_t bh4[4];
                    ldm4(bh4, base + ((nrow * 264 + kcol) << 1));
#pragma unroll
                    for (int mf = 0; mf < 2; mf++) {
                        mma_f16(acc[mf][nb * 2],     ah[mf], bh4[0], bh4[1]);
                        mma_f16(acc[mf][nb * 2 + 1], ah[mf], bh4[2], bh4[3]);
                    }
                }
            }
        }
        __syncthreads();
        // prefetch next m-tile's first two A stages behind the epilogue
        if (mi + 1 < 4) {
            int m0n = (mtg + mi + 1) << 7;
            issueA(m0n, 0, 0); CP_COMMIT();
            issueA(m0n, 1, 1); CP_COMMIT();
        }
        // epilogue: register-only pixel-shuffle stores
#pragma unroll
        for (int mf = 0; mf < 2; mf++) {
#pragma unroll
            for (int which = 0; which < 2; which++) {
                int mm = m0 + wm * 32 + mf * 16 + g + which * 8;
                float bias = g_bf[mm];
                int cch = mm >> 2, r = (mm >> 1) & 1, s2 = mm & 1;
                float* rowp = out + ((size_t)(bimg * 256 + cch) * 128 + 2 * hrow + r) * 128 + s2;
#pragma unroll
                for (int nf = 0; nf < 8; nf++) {
                    int w0 = nf * 8 + 2 * q;
                    rowp[2 * w0]     = acc[mf][nf][which * 2 + 0] + bias;
                    rowp[2 * w0 + 2] = acc[mf][nf][which * 2 + 1] + bias;
                }
            }
        }
    }
}

// ---------------------------------------------------------------------------
extern "C" void kernel_launch(void* const* d_in, const int* in_sizes, int n_in,
                              void* d_out, int out_size)
{
    const float* x    = (const float*)d_in[0];
    const float* wq   = (const float*)d_in[1];
    const float* wkv  = (const float*)d_in[2];
    const float* wo   = (const float*)d_in[3];
    const float* bo   = (const float*)d_in[4];
    const float* relh = (const float*)d_in[5];
    const float* relw = (const float*)d_in[6];
    const float* wc   = (const float*)d_in[7];
    const float* bc   = (const float*)d_in[8];
    float* out = (float*)d_out;

    cudaFuncSetAttribute(k_qkv_tc,  cudaFuncAttributeMaxDynamicSharedMemorySize, QK_SMEM);
    cudaFuncSetAttribute(k_attn_tc, cudaFuncAttributeMaxDynamicSharedMemorySize, AT_SMEM);
    cudaFuncSetAttribute(k_out_tc,  cudaFuncAttributeMaxDynamicSharedMemorySize, KO_SMEM);

    k_fuse<<<256, 256>>>(wo, bo, wc, bc);
    k_splitw<<<768, 256>>>(wq, wkv);
    k_splitx<<<8192, 256>>>(x);
    k_qkv_tc<<<dim3(256, 2), 256, QK_SMEM>>>();
    k_attn_tc<<<dim3(512, 4), 256, AT_SMEM>>>(relh, relw);
    k_out_tc<<<dim3(256, 2), 256, KO_SMEM>>>(out);
}

// round 12
// speedup vs baseline: 1.4809x; 1.4809x over previous
#include <cuda_runtime.h>
#include <cuda_fp16.h>
#include <stdint.h>

#define NPIX 32768            // B*H*W
#define QKVC 768

// Scratch (device globals; 16B-aligned)
__device__ __align__(16) __half g_qh[NPIX * QKVC];  // qkv fp16, [pixel][q|k|v]
__device__ __align__(16) __half g_bh[NPIX * 256];   // attn out fp16, [n][256]
__device__ __align__(16) __half g_wfh[1024 * 256];  // fused conv W fp16, [m][k]
__device__ __align__(16) __half g_wqh[QKVC * 256];  // qkv W fp16 (q pre-scaled), [m][k]
__device__ __align__(16) __half g_xh[256 * NPIX];   // x fp16, [k][n]
__device__ float g_bf[1024];

// ---------------------------------------------------------------------------
// helpers (non-arch-specific PTX only: cp.async / ldmatrix / mma.sync)
// ---------------------------------------------------------------------------
__device__ __forceinline__ uint32_t smem_u32(const void* p) {
    uint32_t a;
    asm("{ .reg .u64 t; cvta.to.shared.u64 t, %1; cvt.u32.u64 %0, t; }" : "=r"(a) : "l"(p));
    return a;
}
__device__ __forceinline__ void cp16(uint32_t d, const void* s) {
    asm volatile("cp.async.ca.shared.global [%0], [%1], 16;" :: "r"(d), "l"(s));
}
#define CP_COMMIT() asm volatile("cp.async.commit_group;")
#define CP_WAIT1()  asm volatile("cp.async.wait_group 1;")
#define CP_WAIT0()  asm volatile("cp.async.wait_group 0;")

__device__ __forceinline__ void ldm4(uint32_t* r, uint32_t a) {
    asm volatile("ldmatrix.sync.aligned.m8n8.x4.shared.b16 {%0,%1,%2,%3}, [%4];"
                 : "=r"(r[0]), "=r"(r[1]), "=r"(r[2]), "=r"(r[3]) : "r"(a));
}
__device__ __forceinline__ void ldm4t(uint32_t* r, uint32_t a) {
    asm volatile("ldmatrix.sync.aligned.m8n8.x4.trans.shared.b16 {%0,%1,%2,%3}, [%4];"
                 : "=r"(r[0]), "=r"(r[1]), "=r"(r[2]), "=r"(r[3]) : "r"(a));
}
__device__ __forceinline__ void mma_f16(float* d, const uint32_t* a, uint32_t b0, uint32_t b1) {
    asm volatile("mma.sync.aligned.m16n8k16.row.col.f32.f16.f16.f32 "
                 "{%0,%1,%2,%3}, {%4,%5,%6,%7}, {%8,%9}, {%0,%1,%2,%3};"
                 : "+f"(d[0]), "+f"(d[1]), "+f"(d[2]), "+f"(d[3])
                 : "r"(a[0]), "r"(a[1]), "r"(a[2]), "r"(a[3]), "r"(b0), "r"(b1));
}
__device__ __forceinline__ uint32_t packh(__half a, __half b) {
    return (uint32_t)__half_as_ushort(a) | ((uint32_t)__half_as_ushort(b) << 16);
}

// ---------------------------------------------------------------------------
// K0: fuse wo into conv: Wf = wc @ wo (fp16), bf = wc@bo + bc
// ---------------------------------------------------------------------------
__global__ __launch_bounds__(256) void k_fuse(const float* __restrict__ wo,
                                              const float* __restrict__ bo,
                                              const float* __restrict__ wc,
                                              const float* __restrict__ bc)
{
    int ob = blockIdx.x * 4;
    int i  = threadIdx.x;
    float a0 = 0.f, a1 = 0.f, a2 = 0.f, a3 = 0.f;
    for (int cc = 0; cc < 256; cc++) {
        float w = wo[cc * 256 + i];
        a0 += wc[(ob + 0) * 256 + cc] * w;
        a1 += wc[(ob + 1) * 256 + cc] * w;
        a2 += wc[(ob + 2) * 256 + cc] * w;
        a3 += wc[(ob + 3) * 256 + cc] * w;
    }
    float vals[4] = {a0, a1, a2, a3};
#pragma unroll
    for (int j = 0; j < 4; j++)
        g_wfh[(size_t)(ob + j) * 256 + i] = __float2half_rn(vals[j]);
    if (i < 4) {
        int o = ob + i;
        float s = 0.f;
        for (int c2 = 0; c2 < 256; c2++) s += wc[o * 256 + c2] * bo[c2];
        g_bf[o] = s + bc[o];
    }
}

// ---------------------------------------------------------------------------
// K0b: wq (pre-scaled by 0.125) / wkv -> fp16 row-major [768][256]
// ---------------------------------------------------------------------------
__global__ __launch_bounds__(256) void k_splitw(const float* __restrict__ wq,
                                                const float* __restrict__ wkv)
{
    int i = blockIdx.x * 256 + threadIdx.x;
    int m = i >> 8, c = i & 255;
    float v = (m < 256) ? wq[m * 256 + c] * 0.125f : wkv[(m - 256) * 256 + c];
    g_wqh[i] = __float2half_rn(v);
}

// ---------------------------------------------------------------------------
// K0c: x -> fp16 [k=channel][n=b*4096+p]
// ---------------------------------------------------------------------------
__global__ __launch_bounds__(256) void k_splitx(const float* __restrict__ x)
{
    size_t i = (size_t)(blockIdx.x * 256 + threadIdx.x) * 4;
    float4 v = *(const float4*)(x + i);
    size_t o = (size_t)((i >> 12) & 255) * NPIX + ((i >> 20) << 12) + (i & 4095);
    *(uint2*)&g_xh[o] = make_uint2(packh(__float2half_rn(v.x), __float2half_rn(v.y)),
                                   packh(__float2half_rn(v.z), __float2half_rn(v.w)));
}

// ---------------------------------------------------------------------------
// K1: QKV projection. C[768,32768] = W @ X, fp16 single-term.
// 3-stage cp.async ring, one __syncthreads per stage. (R10 design.)
// ---------------------------------------------------------------------------
#define QK_BUF  18944
#define QK_SMEM (QK_BUF * 3)

__global__ void __launch_bounds__(256, 2) k_qkv_tc()
{
    extern __shared__ char qsm[];
    uint32_t base = smem_u32(qsm);
    int tid = threadIdx.x, lane = tid & 31, wrp = tid >> 5;
    int wm = wrp >> 1, wn = wrp & 1;
    int mt = blockIdx.y, n0 = blockIdx.x << 7;
    int m0 = mt << 7;

    float acc[2][8][4];
#pragma unroll
    for (int a = 0; a < 2; a++)
#pragma unroll
        for (int b = 0; b < 8; b++)
#pragma unroll
            for (int c = 0; c < 4; c++) acc[a][b][c] = 0.f;

    int ar = tid >> 1, ac = (tid & 1) << 4;
    int br = tid >> 3, bc = (tid & 7) << 4;

    auto issue = [&](int s, int buf) {
        int kk = s << 5;
        uint32_t qa = base + buf * QK_BUF;
        const __half* A = g_wqh + (size_t)(m0 + ar) * 256 + kk + ac;
        uint32_t da = qa + ((ar * 40 + ac) << 1);
        cp16(da, A); cp16(da + 16, A + 8);
        const __half* B = g_xh + (size_t)(kk + br) * NPIX + n0 + bc;
        uint32_t db = qa + 10240 + ((br * 136 + bc) << 1);
        cp16(db, B); cp16(db + 16, B + 8);
    };
    auto compute = [&](int buf) {
        uint32_t qa = base + buf * QK_BUF;
        uint32_t ab = qa, bb = qa + 10240;
#pragma unroll
        for (int kh = 0; kh < 32; kh += 16) {
            uint32_t ah[2][4];
#pragma unroll
            for (int mf = 0; mf < 2; mf++)
                ldm4(ah[mf], ab + (((wm * 32 + mf * 16 + (lane & 15)) * 40
                                   + kh + ((lane >> 4) << 3)) << 1));
#pragma unroll
            for (int nb = 0; nb < 4; nb++) {
                uint32_t bh4[4];
                ldm4t(bh4, bb + (((kh + ((lane >> 3) & 1) * 8 + (lane & 7)) * 136
                                  + wn * 64 + nb * 16 + ((lane >> 4) << 3)) << 1));
#pragma unroll
                for (int mf = 0; mf < 2; mf++) {
                    mma_f16(acc[mf][nb * 2],     ah[mf], bh4[0], bh4[1]);
                    mma_f16(acc[mf][nb * 2 + 1], ah[mf], bh4[2], bh4[3]);
                }
            }
        }
    };

    issue(0, 0); CP_COMMIT();
    issue(1, 1); CP_COMMIT();
    for (int s = 0; s < 8; s++) {
        if (s < 7) CP_WAIT1(); else CP_WAIT0();
        __syncthreads();
        if (s + 2 < 8) { issue(s + 2, (s + 2) % 3); CP_COMMIT(); }
        compute(s % 3);
    }
    __syncthreads();

    // epilogue: transpose per 32-row m-quarter via smem; write fp16
    float* tb = (float*)qsm;
    int g = lane >> 2, q = lane & 3;
#pragma unroll
    for (int mq = 0; mq < 4; mq++) {
        if (wm == mq) {
#pragma unroll
            for (int mf = 0; mf < 2; mf++)
#pragma unroll
                for (int nf = 0; nf < 8; nf++) {
                    int nl = wn * 64 + nf * 8 + q * 2;
                    int ml = mf * 16 + g;
                    tb[nl * 33 + ml]            = acc[mf][nf][0];
                    tb[(nl + 1) * 33 + ml]      = acc[mf][nf][1];
                    tb[nl * 33 + ml + 8]        = acc[mf][nf][2];
                    tb[(nl + 1) * 33 + ml + 8]  = acc[mf][nf][3];
                }
        }
        __syncthreads();
        int nl = tid >> 1, half2 = tid & 1;
        const float* src = tb + nl * 33 + half2 * 16;
        size_t dst = (size_t)(n0 + nl) * QKVC + m0 + mq * 32 + half2 * 16;
        unsigned short hs[16];
#pragma unroll
        for (int u = 0; u < 16; u++)
            hs[u] = __half_as_ushort(__float2half_rn(src[u]));
        *(uint4*)&g_qh[dst]     = *(uint4*)&hs[0];
        *(uint4*)&g_qh[dst + 8] = *(uint4*)&hs[8];
        __syncthreads();
    }
}

// ---------------------------------------------------------------------------
// K2: tensor-core halo attention (rel logits via MMA; dual-buffer reduction).
// ---------------------------------------------------------------------------
#define AT_SQ    0
#define AT_SK    9216
#define AT_RELH  46080
#define AT_RELW  50688
#define AT_GW    55296
#define AT_GH    63744
#define AT_RMX   72192
#define AT_RSUM  72704
#define AT_RED2  73216
#define AT_SMEM  90624

__global__ void __launch_bounds__(256, 2) k_attn_tc(const float* __restrict__ relh,
                                                    const float* __restrict__ relw)
{
    extern __shared__ char smc[];
    uint32_t sb = smem_u32(smc);
    int t = threadIdx.x, lane = t & 31, wid = t >> 5;
    int wm = wid >> 1, wn = wid & 1;
    int nbk = blockIdx.x, hh = blockIdx.y;
    int bi = nbk >> 6, tbw = nbk & 63;
    int bh = tbw >> 3, bw = tbw & 7;
    int hco = hh * 64;

    uint32_t qB = sb + AT_SQ;
    uint32_t kB = sb + AT_SK;

    {
        int chunk = t & 7, rr = t >> 3;
        {
            int row = rr;
            int qx = row >> 3, qy = row & 7;
            size_t pix = (size_t)(bi * 4096 + (bh * 8 + qx) * 64 + bw * 8 + qy) * QKVC + hco;
            ((uint4*)(smc + AT_SQ))[row * 9 + chunk] = *(const uint4*)(g_qh + pix + chunk * 8);
            row = rr + 32;
            qx = row >> 3; qy = row & 7;
            pix = (size_t)(bi * 4096 + (bh * 8 + qx) * 64 + bw * 8 + qy) * QKVC + hco;
            ((uint4*)(smc + AT_SQ))[row * 9 + chunk] = *(const uint4*)(g_qh + pix + chunk * 8);
        }
#pragma unroll
        for (int p = 0; p < 8; p++) {
            int row = p * 32 + rr;
            int ki = row >> 4, kj = row & 15;
            int gh = bh * 8 - 4 + ki, gw = bw * 8 - 4 + kj;
            bool valid = ((unsigned)gh < 64u) && ((unsigned)gw < 64u);
            size_t pix = (size_t)(valid ? bi * 4096 + gh * 64 + gw : bi * 4096) * QKVC
                       + 256 + hco + chunk * 8;
            uint4 z = make_uint4(0, 0, 0, 0);
            ((uint4*)(smc + AT_SK))[row * 9 + chunk] = valid ? *(const uint4*)(g_qh + pix) : z;
        }
        for (int idx = t; idx < 1152; idx += 256) {
            ((uint32_t*)(smc + AT_RELH))[idx] = 0;
            ((uint32_t*)(smc + AT_RELW))[idx] = 0;
        }
        __syncthreads();
        for (int idx = t; idx < 1984; idx += 256) {
            int r = idx >> 6, dd = idx & 63;
            ((__half*)(smc + AT_RELH))[r * 72 + dd] = __float2half_rn(relh[idx]);
            ((__half*)(smc + AT_RELW))[r * 72 + dd] = __float2half_rn(relw[idx]);
        }
    }
    __syncthreads();

    // ---- rel logits via MMA: wn==0 -> Gw, wn==1 -> Gh ----
    {
        float racc[4][4];
#pragma unroll
        for (int a = 0; a < 4; a++)
#pragma unroll
            for (int b = 0; b < 4; b++) racc[a][b] = 0.f;
        uint32_t relB = sb + (wn ? AT_RELH : AT_RELW);
#pragma unroll
        for (int kt = 0; kt < 4; kt++) {
            uint32_t ah[4];
            ldm4(ah, qB + (((wm * 16 + (lane & 15)) * 72 + kt * 16 + ((lane >> 4) << 3)) << 1));
#pragma unroll
            for (int nb = 0; nb < 2; nb++) {
                uint32_t bh4[4];
                ldm4(bh4, relB + (((nb * 16 + ((lane >> 4) << 3) + (lane & 7)) * 72
                                   + kt * 16 + (((lane >> 3) & 1) << 3)) << 1));
                mma_f16(racc[nb * 2],     ah, bh4[0], bh4[1]);
                mma_f16(racc[nb * 2 + 1], ah, bh4[2], bh4[3]);
            }
        }
        float* G = (float*)(smc + (wn ? AT_GH : AT_GW));
        int g2 = lane >> 2, tt = lane & 3;
#pragma unroll
        for (int j = 0; j < 4; j++)
#pragma unroll
            for (int e = 0; e < 4; e++) {
                int row = wm * 16 + g2 + ((e >= 2) ? 8 : 0);
                int col = j * 8 + 2 * tt + (e & 1);
                G[row * 33 + col] = racc[j][e];
            }
    }

    // ---- QK^T ----
    float s[16][4];
#pragma unroll
    for (int a = 0; a < 16; a++)
#pragma unroll
        for (int b = 0; b < 4; b++) s[a][b] = 0.f;
#pragma unroll
    for (int kt = 0; kt < 4; kt++) {
        uint32_t ah[4];
        ldm4(ah, qB + (((wm * 16 + (lane & 15)) * 72 + kt * 16 + ((lane >> 4) << 3)) << 1));
#pragma unroll
        for (int nb = 0; nb < 8; nb++) {
            uint32_t boff = (((wn * 128 + nb * 16 + ((lane >> 4) << 3) + (lane & 7)) * 72
                             + kt * 16 + (((lane >> 3) & 1) << 3)) << 1);
            uint32_t bh4[4];
            ldm4(bh4, kB + boff);
            mma_f16(s[nb * 2],     ah, bh4[0], bh4[1]);
            mma_f16(s[nb * 2 + 1], ah, bh4[2], bh4[3]);
        }
    }
    __syncthreads();

    // ---- prefetch V into K buffer ----
    {
        int chunk = t & 7, rr = t >> 3;
#pragma unroll
        for (int p = 0; p < 8; p++) {
            int row = p * 32 + rr;
            int ki = row >> 4, kj = row & 15;
            int gh = bh * 8 - 4 + ki, gw = bw * 8 - 4 + kj;
            bool valid = ((unsigned)gh < 64u) && ((unsigned)gw < 64u);
            size_t pix = (size_t)(valid ? bi * 4096 + gh * 64 + gw : bi * 4096) * QKVC
                       + 512 + hco + chunk * 8;
            cp16(kB + ((uint32_t)(row * 9 + chunk) << 4), g_qh + pix);
        }
        CP_COMMIT();
    }

    // ---- fixup: rel logits + mask ----
    {
        const float* Gw = (const float*)(smc + AT_GW);
        const float* Gh = (const float*)(smc + AT_GH);
        int g = lane >> 2, tt = lane & 3;
#pragma unroll
        for (int nt = 0; nt < 16; nt++) {
            int jbase = wn * 128 + nt * 8 + 2 * tt;
#pragma unroll
            for (int e = 0; e < 4; e++) {
                int row = wm * 16 + g + ((e >= 2) ? 8 : 0);
                int jj = jbase + (e & 1);
                int ki = jj >> 4, kj = jj & 15;
                int gh = bh * 8 - 4 + ki, gw = bw * 8 - 4 + kj;
                if (((unsigned)gh >= 64u) || ((unsigned)gw >= 64u))
                    s[nt][e] = -3.0e38f;
                else
                    s[nt][e] += Gw[row * 33 + kj - (row & 7) + 15]
                              + Gh[row * 33 + ki - (row >> 3) + 15];
            }
        }
    }

    float* rmx  = (float*)(smc + AT_RMX);
    float* rsum = (float*)(smc + AT_RSUM);
    int gg = lane >> 2;
    int rA = wm * 16 + gg, rB = rA + 8;
    {
        float mA = -3.4e38f, mB = -3.4e38f;
#pragma unroll
        for (int nt = 0; nt < 16; nt++) {
            mA = fmaxf(mA, fmaxf(s[nt][0], s[nt][1]));
            mB = fmaxf(mB, fmaxf(s[nt][2], s[nt][3]));
        }
        mA = fmaxf(mA, __shfl_xor_sync(0xffffffffu, mA, 1));
        mA = fmaxf(mA, __shfl_xor_sync(0xffffffffu, mA, 2));
        mB = fmaxf(mB, __shfl_xor_sync(0xffffffffu, mB, 1));
        mB = fmaxf(mB, __shfl_xor_sync(0xffffffffu, mB, 2));
        if ((lane & 3) == 0) { rmx[wn * 64 + rA] = mA; rmx[wn * 64 + rB] = mB; }
    }
    __syncthreads();
    {
        float mA = fmaxf(rmx[rA], rmx[64 + rA]);
        float mB = fmaxf(rmx[rB], rmx[64 + rB]);
        float sA = 0.f, sB = 0.f;
#pragma unroll
        for (int nt = 0; nt < 16; nt++) {
            s[nt][0] = __expf(s[nt][0] - mA); sA += s[nt][0];
            s[nt][1] = __expf(s[nt][1] - mA); sA += s[nt][1];
            s[nt][2] = __expf(s[nt][2] - mB); sB += s[nt][2];
            s[nt][3] = __expf(s[nt][3] - mB); sB += s[nt][3];
        }
        sA += __shfl_xor_sync(0xffffffffu, sA, 1);
        sA += __shfl_xor_sync(0xffffffffu, sA, 2);
        sB += __shfl_xor_sync(0xffffffffu, sB, 1);
        sB += __shfl_xor_sync(0xffffffffu, sB, 2);
        if ((lane & 3) == 0) { rsum[wn * 64 + rA] = sA; rsum[wn * 64 + rB] = sB; }
    }
    __syncthreads();
    {
        float invA = 1.0f / (rsum[rA] + rsum[64 + rA]);
        float invB = 1.0f / (rsum[rB] + rsum[64 + rB]);
#pragma unroll
        for (int nt = 0; nt < 16; nt++) {
            __half h0 = __float2half_rn(s[nt][0] * invA);
            __half h1 = __float2half_rn(s[nt][1] * invA);
            __half h2 = __float2half_rn(s[nt][2] * invB);
            __half h3 = __float2half_rn(s[nt][3] * invB);
            s[nt][0] = __uint_as_float(packh(h0, h1));
            s[nt][1] = __uint_as_float(packh(h2, h3));
        }
    }
    CP_WAIT0();
    __syncthreads();

    // ---- AV ----
    float avc[8][4];
#pragma unroll
    for (int a = 0; a < 8; a++)
#pragma unroll
        for (int b = 0; b < 4; b++) avc[a][b] = 0.f;
#pragma unroll
    for (int kt2 = 0; kt2 < 8; kt2++) {
        uint32_t pa[4] = { __float_as_uint(s[2 * kt2][0]), __float_as_uint(s[2 * kt2][1]),
                           __float_as_uint(s[2 * kt2 + 1][0]), __float_as_uint(s[2 * kt2 + 1][1]) };
#pragma unroll
        for (int nb = 0; nb < 4; nb++) {
            uint32_t off = (((wn * 128 + kt2 * 16 + ((lane >> 3) & 1) * 8 + (lane & 7)) * 72
                            + nb * 16 + ((lane >> 4) << 3)) << 1);
            uint32_t vh4[4];
            ldm4t(vh4, kB + off);
            mma_f16(avc[nb * 2],     pa, vh4[0], vh4[1]);
            mma_f16(avc[nb * 2 + 1], pa, vh4[2], vh4[3]);
        }
    }

    // dual-buffer reduction: wn==0 -> Red1 (overlays sK), wn==1 -> Red2
    float* Red1 = (float*)(smc + AT_SK);
    float* Red2 = (float*)(smc + AT_RED2);
    __syncthreads();
    {
        float* Rd = wn ? Red2 : Red1;
#pragma unroll
        for (int nf = 0; nf < 8; nf++)
#pragma unroll
            for (int e = 0; e < 4; e++) {
                int row = wm * 16 + gg + ((e >= 2) ? 8 : 0);
                int col = nf * 8 + 2 * (lane & 3) + (e & 1);
                Rd[row * 68 + col] = avc[nf][e];
            }
    }
    __syncthreads();

    {
        int qi = t >> 2, c0 = (t & 3) * 16;
        int qx = qi >> 3, qy = qi & 7;
        size_t base = (size_t)(bi * 4096 + (bh * 8 + qx) * 64 + bw * 8 + qy) * 256 + hco + c0;
        unsigned short hs[16];
#pragma unroll
        for (int u = 0; u < 16; u++)
            hs[u] = __half_as_ushort(__float2half_rn(Red1[qi * 68 + c0 + u]
                                                   + Red2[qi * 68 + c0 + u]));
        *(uint4*)&g_bh[base]     = *(uint4*)&hs[0];
        *(uint4*)&g_bh[base + 8] = *(uint4*)&hs[8];
    }
}

// ---------------------------------------------------------------------------
// K3: output GEMM + PixelShuffle. fp16 single-term, 3-stage ring. (R10 design.)
// ---------------------------------------------------------------------------
#define KO_BUF  20480
#define KO_SMEM (KO_BUF * 3)

__global__ void __launch_bounds__(256, 2) k_out_tc(float* __restrict__ out)
{
    extern __shared__ char osm[];
    uint32_t base = smem_u32(osm);
    int tid = threadIdx.x, lane = tid & 31, wrp = tid >> 5;
    int wm = wrp >> 1, wn = wrp & 1;
    int mt = blockIdx.y, n0 = blockIdx.x << 7;
    int m0 = mt << 7;

    float acc[2][8][4];
#pragma unroll
    for (int a = 0; a < 2; a++)
#pragma unroll
        for (int b = 0; b < 8; b++)
#pragma unroll
            for (int c = 0; c < 4; c++) acc[a][b][c] = 0.f;

    int ar = tid >> 1, ac = (tid & 1) << 4;

    auto issue = [&](int s, int buf) {
        int kk = s << 5;
        uint32_t qa = base + buf * KO_BUF;
        const __half* A = g_wfh + (size_t)(m0 + ar) * 256 + kk + ac;
        uint32_t da = qa + ((ar * 40 + ac) << 1);
        cp16(da, A); cp16(da + 16, A + 8);
        const __half* B = g_bh + (size_t)(n0 + ar) * 256 + kk + ac;
        uint32_t db = qa + 10240 + ((ar * 40 + ac) << 1);
        cp16(db, B); cp16(db + 16, B + 8);
    };
    auto compute = [&](int buf) {
        uint32_t qa = base + buf * KO_BUF;
        uint32_t ab = qa, bb = qa + 10240;
#pragma unroll
        for (int kh = 0; kh < 32; kh += 16) {
            uint32_t ah[2][4];
#pragma unroll
            for (int mf = 0; mf < 2; mf++)
                ldm4(ah[mf], ab + (((wm * 32 + mf * 16 + (lane & 15)) * 40
                                   + kh + ((lane >> 4) << 3)) << 1));
#pragma unroll
            for (int nb = 0; nb < 4; nb++) {
                uint32_t bh4[4];
                ldm4(bh4, bb + (((wn * 64 + nb * 16 + ((lane >> 4) << 3) + (lane & 7)) * 40
                                 + kh + (((lane >> 3) & 1) << 3)) << 1));
#pragma unroll
                for (int mf = 0; mf < 2; mf++) {
                    mma_f16(acc[mf][nb * 2],     ah[mf], bh4[0], bh4[1]);
                    mma_f16(acc[mf][nb * 2 + 1], ah[mf], bh4[2], bh4[3]);
                }
            }
        }
    };

    issue(0, 0); CP_COMMIT();
    issue(1, 1); CP_COMMIT();
    for (int s = 0; s < 8; s++) {
        if (s < 7) CP_WAIT1(); else CP_WAIT0();
        __syncthreads();
        if (s + 2 < 8) { issue(s + 2, (s + 2) % 3); CP_COMMIT(); }
        compute(s % 3);
    }

    int g = lane >> 2, q = lane & 3;
    int h0 = (n0 & 4095) >> 6, bimg = n0 >> 12;
    int hrow = h0 + wn;
#pragma unroll
    for (int mf = 0; mf < 2; mf++) {
#pragma unroll
        for (int which = 0; which < 2; which++) {
            int mm = m0 + wm * 32 + mf * 16 + g + which * 8;
            float bias = g_bf[mm];
            int cch = mm >> 2, r = (mm >> 1) & 1, s2 = mm & 1;
            float* rowp = out + ((size_t)(bimg * 256 + cch) * 128 + 2 * hrow + r) * 128 + s2;
#pragma unroll
            for (int nf = 0; nf < 8; nf++) {
                int w0 = nf * 8 + 2 * q;
                rowp[2 * w0]     = acc[mf][nf][which * 2 + 0] + bias;
                rowp[2 * w0 + 2] = acc[mf][nf][which * 2 + 1] + bias;
            }
        }
    }
}

// ---------------------------------------------------------------------------
extern "C" void kernel_launch(void* const* d_in, const int* in_sizes, int n_in,
                              void* d_out, int out_size)
{
    const float* x    = (const float*)d_in[0];
    const float* wq   = (const float*)d_in[1];
    const float* wkv  = (const float*)d_in[2];
    const float* wo   = (const float*)d_in[3];
    const float* bo   = (const float*)d_in[4];
    const float* relh = (const float*)d_in[5];
    const float* relw = (const float*)d_in[6];
    const float* wc   = (const float*)d_in[7];
    const float* bc   = (const float*)d_in[8];
    float* out = (float*)d_out;

    cudaFuncSetAttribute(k_qkv_tc,  cudaFuncAttributeMaxDynamicSharedMemorySize, QK_SMEM);
    cudaFuncSetAttribute(k_attn_tc, cudaFuncAttributeMaxDynamicSharedMemorySize, AT_SMEM);
    cudaFuncSetAttribute(k_out_tc,  cudaFuncAttributeMaxDynamicSharedMemorySize, KO_SMEM);

    k_fuse<<<256, 256>>>(wo, bo, wc, bc);
    k_splitw<<<768, 256>>>(wq, wkv);
    k_splitx<<<8192, 256>>>(x);
    k_qkv_tc<<<dim3(256, 6), 256, QK_SMEM>>>();
    k_attn_tc<<<dim3(512, 4), 256, AT_SMEM>>>(relh, relw);
    k_out_tc<<<dim3(256, 8), 256, KO_SMEM>>>(out);
}

// round 13
// speedup vs baseline: 1.5921x; 1.0750x over previous
#include <cuda_runtime.h>
#include <cuda_fp16.h>
#include <stdint.h>

#define NPIX 32768            // B*H*W
#define QKVC 768

// Scratch (device globals; 16B-aligned)
__device__ __align__(16) __half g_qh[NPIX * QKVC];  // qkv fp16, [pixel][q|k|v]
__device__ __align__(16) __half g_bh[NPIX * 256];   // attn out fp16, [n][256]
__device__ __align__(16) __half g_wfh[1024 * 256];  // fused conv W fp16, [m][k]
__device__ __align__(16) __half g_wqh[QKVC * 256];  // qkv W fp16 (q pre-scaled), [m][k]
__device__ __align__(16) __half g_xh[256 * NPIX];   // x fp16, [k][n]
__device__ float g_bf[1024];

// ---------------------------------------------------------------------------
// helpers (non-arch-specific PTX only: cp.async / ldmatrix / mma.sync)
// ---------------------------------------------------------------------------
__device__ __forceinline__ uint32_t smem_u32(const void* p) {
    uint32_t a;
    asm("{ .reg .u64 t; cvta.to.shared.u64 t, %1; cvt.u32.u64 %0, t; }" : "=r"(a) : "l"(p));
    return a;
}
__device__ __forceinline__ void cp16(uint32_t d, const void* s) {
    asm volatile("cp.async.cg.shared.global [%0], [%1], 16;" :: "r"(d), "l"(s));
}
// zero-fill variant: copies src_size bytes, zero-pads to 16
__device__ __forceinline__ void cp16z(uint32_t d, const void* s, uint32_t sz) {
    asm volatile("cp.async.cg.shared.global [%0], [%1], 16, %2;" :: "r"(d), "l"(s), "r"(sz));
}
#define CP_COMMIT() asm volatile("cp.async.commit_group;")
#define CP_WAIT2()  asm volatile("cp.async.wait_group 2;")
#define CP_WAIT1()  asm volatile("cp.async.wait_group 1;")
#define CP_WAIT0()  asm volatile("cp.async.wait_group 0;")

__device__ __forceinline__ void ldm4(uint32_t* r, uint32_t a) {
    asm volatile("ldmatrix.sync.aligned.m8n8.x4.shared.b16 {%0,%1,%2,%3}, [%4];"
                 : "=r"(r[0]), "=r"(r[1]), "=r"(r[2]), "=r"(r[3]) : "r"(a));
}
__device__ __forceinline__ void ldm4t(uint32_t* r, uint32_t a) {
    asm volatile("ldmatrix.sync.aligned.m8n8.x4.trans.shared.b16 {%0,%1,%2,%3}, [%4];"
                 : "=r"(r[0]), "=r"(r[1]), "=r"(r[2]), "=r"(r[3]) : "r"(a));
}
__device__ __forceinline__ void mma_f16(float* d, const uint32_t* a, uint32_t b0, uint32_t b1) {
    asm volatile("mma.sync.aligned.m16n8k16.row.col.f32.f16.f16.f32 "
                 "{%0,%1,%2,%3}, {%4,%5,%6,%7}, {%8,%9}, {%0,%1,%2,%3};"
                 : "+f"(d[0]), "+f"(d[1]), "+f"(d[2]), "+f"(d[3])
                 : "r"(a[0]), "r"(a[1]), "r"(a[2]), "r"(a[3]), "r"(b0), "r"(b1));
}
__device__ __forceinline__ uint32_t packh(__half a, __half b) {
    return (uint32_t)__half_as_ushort(a) | ((uint32_t)__half_as_ushort(b) << 16);
}

// ---------------------------------------------------------------------------
// K0: fuse wo into conv: Wf = wc @ wo (fp16), bf = wc@bo + bc
// ---------------------------------------------------------------------------
__global__ __launch_bounds__(256) void k_fuse(const float* __restrict__ wo,
                                              const float* __restrict__ bo,
                                              const float* __restrict__ wc,
                                              const float* __restrict__ bc)
{
    int ob = blockIdx.x * 4;
    int i  = threadIdx.x;
    float a0 = 0.f, a1 = 0.f, a2 = 0.f, a3 = 0.f;
    for (int cc = 0; cc < 256; cc++) {
        float w = wo[cc * 256 + i];
        a0 += wc[(ob + 0) * 256 + cc] * w;
        a1 += wc[(ob + 1) * 256 + cc] * w;
        a2 += wc[(ob + 2) * 256 + cc] * w;
        a3 += wc[(ob + 3) * 256 + cc] * w;
    }
    float vals[4] = {a0, a1, a2, a3};
#pragma unroll
    for (int j = 0; j < 4; j++)
        g_wfh[(size_t)(ob + j) * 256 + i] = __float2half_rn(vals[j]);
    if (i < 4) {
        int o = ob + i;
        float s = 0.f;
        for (int c2 = 0; c2 < 256; c2++) s += wc[o * 256 + c2] * bo[c2];
        g_bf[o] = s + bc[o];
    }
}

// ---------------------------------------------------------------------------
// K0b: wq (pre-scaled by 0.125) / wkv -> fp16 row-major [768][256]
// ---------------------------------------------------------------------------
__global__ __launch_bounds__(256) void k_splitw(const float* __restrict__ wq,
                                                const float* __restrict__ wkv)
{
    int i = blockIdx.x * 256 + threadIdx.x;
    int m = i >> 8, c = i & 255;
    float v = (m < 256) ? wq[m * 256 + c] * 0.125f : wkv[(m - 256) * 256 + c];
    g_wqh[i] = __float2half_rn(v);
}

// ---------------------------------------------------------------------------
// K0c: x -> fp16 [k=channel][n=b*4096+p]
// ---------------------------------------------------------------------------
__global__ __launch_bounds__(256) void k_splitx(const float* __restrict__ x)
{
    size_t i = (size_t)(blockIdx.x * 256 + threadIdx.x) * 4;
    float4 v = *(const float4*)(x + i);
    size_t o = (size_t)((i >> 12) & 255) * NPIX + ((i >> 20) << 12) + (i & 4095);
    *(uint2*)&g_xh[o] = make_uint2(packh(__float2half_rn(v.x), __float2half_rn(v.y)),
                                   packh(__float2half_rn(v.z), __float2half_rn(v.w)));
}

// ---------------------------------------------------------------------------
// K1: QKV projection. C[768,32768] = W @ X, fp16 single-term.
// 4-stage cp.async ring (cg), fully unrolled stage loop.
// ---------------------------------------------------------------------------
#define QK_BUF  18944
#define QK_SMEM (QK_BUF * 4)

__global__ void __launch_bounds__(256, 2) k_qkv_tc()
{
    extern __shared__ char qsm[];
    uint32_t base = smem_u32(qsm);
    int tid = threadIdx.x, lane = tid & 31, wrp = tid >> 5;
    int wm = wrp >> 1, wn = wrp & 1;
    int mt = blockIdx.y, n0 = blockIdx.x << 7;
    int m0 = mt << 7;

    float acc[2][8][4];
#pragma unroll
    for (int a = 0; a < 2; a++)
#pragma unroll
        for (int b = 0; b < 8; b++)
#pragma unroll
            for (int c = 0; c < 4; c++) acc[a][b][c] = 0.f;

    int ar = tid >> 1, ac = (tid & 1) << 4;
    int br = tid >> 3, bc = (tid & 7) << 4;

    auto issue = [&](int s, int buf) {
        int kk = s << 5;
        uint32_t qa = base + buf * QK_BUF;
        const __half* A = g_wqh + (size_t)(m0 + ar) * 256 + kk + ac;
        uint32_t da = qa + ((ar * 40 + ac) << 1);
        cp16(da, A); cp16(da + 16, A + 8);
        const __half* B = g_xh + (size_t)(kk + br) * NPIX + n0 + bc;
        uint32_t db = qa + 10240 + ((br * 136 + bc) << 1);
        cp16(db, B); cp16(db + 16, B + 8);
    };
    auto compute = [&](int buf) {
        uint32_t qa = base + buf * QK_BUF;
        uint32_t ab = qa, bb = qa + 10240;
#pragma unroll
        for (int kh = 0; kh < 32; kh += 16) {
            uint32_t ah[2][4];
#pragma unroll
            for (int mf = 0; mf < 2; mf++)
                ldm4(ah[mf], ab + (((wm * 32 + mf * 16 + (lane & 15)) * 40
                                   + kh + ((lane >> 4) << 3)) << 1));
#pragma unroll
            for (int nb = 0; nb < 4; nb++) {
                uint32_t bh4[4];
                ldm4t(bh4, bb + (((kh + ((lane >> 3) & 1) * 8 + (lane & 7)) * 136
                                  + wn * 64 + nb * 16 + ((lane >> 4) << 3)) << 1));
#pragma unroll
                for (int mf = 0; mf < 2; mf++) {
                    mma_f16(acc[mf][nb * 2],     ah[mf], bh4[0], bh4[1]);
                    mma_f16(acc[mf][nb * 2 + 1], ah[mf], bh4[2], bh4[3]);
                }
            }
        }
    };

    issue(0, 0); CP_COMMIT();
    issue(1, 1); CP_COMMIT();
    issue(2, 2); CP_COMMIT();
#pragma unroll
    for (int s = 0; s < 8; s++) {
        if (s < 6) CP_WAIT2();
        else if (s == 6) CP_WAIT1();
        else CP_WAIT0();
        __syncthreads();
        if (s + 3 < 8) { issue(s + 3, (s + 3) & 3); CP_COMMIT(); }
        compute(s & 3);
    }
    __syncthreads();

    // epilogue: transpose per 32-row m-quarter via smem; write fp16
    float* tb = (float*)qsm;
    int g = lane >> 2, q = lane & 3;
#pragma unroll
    for (int mq = 0; mq < 4; mq++) {
        if (wm == mq) {
#pragma unroll
            for (int mf = 0; mf < 2; mf++)
#pragma unroll
                for (int nf = 0; nf < 8; nf++) {
                    int nl = wn * 64 + nf * 8 + q * 2;
                    int ml = mf * 16 + g;
                    tb[nl * 33 + ml]            = acc[mf][nf][0];
                    tb[(nl + 1) * 33 + ml]      = acc[mf][nf][1];
                    tb[nl * 33 + ml + 8]        = acc[mf][nf][2];
                    tb[(nl + 1) * 33 + ml + 8]  = acc[mf][nf][3];
                }
        }
        __syncthreads();
        int nl = tid >> 1, half2 = tid & 1;
        const float* src = tb + nl * 33 + half2 * 16;
        size_t dst = (size_t)(n0 + nl) * QKVC + m0 + mq * 32 + half2 * 16;
        unsigned short hs[16];
#pragma unroll
        for (int u = 0; u < 16; u++)
            hs[u] = __half_as_ushort(__float2half_rn(src[u]));
        *(uint4*)&g_qh[dst]     = *(uint4*)&hs[0];
        *(uint4*)&g_qh[dst + 8] = *(uint4*)&hs[8];
        __syncthreads();
    }
}

// ---------------------------------------------------------------------------
// K2: tensor-core halo attention (rel logits via MMA; dual-buffer reduction).
// Q/K gathered via cp.async.cg (zero-fill for masked rows).
// ---------------------------------------------------------------------------
#define AT_SQ    0
#define AT_SK    9216
#define AT_RELH  46080
#define AT_RELW  50688
#define AT_GW    55296
#define AT_GH    63744
#define AT_RMX   72192
#define AT_RSUM  72704
#define AT_RED2  73216
#define AT_SMEM  90624

__global__ void __launch_bounds__(256, 2) k_attn_tc(const float* __restrict__ relh,
                                                    const float* __restrict__ relw)
{
    extern __shared__ char smc[];
    uint32_t sb = smem_u32(smc);
    int t = threadIdx.x, lane = t & 31, wid = t >> 5;
    int wm = wid >> 1, wn = wid & 1;
    int nbk = blockIdx.x, hh = blockIdx.y;
    int bi = nbk >> 6, tbw = nbk & 63;
    int bh = tbw >> 3, bw = tbw & 7;
    int hco = hh * 64;

    uint32_t qB = sb + AT_SQ;
    uint32_t kB = sb + AT_SK;

    {
        int chunk = t & 7, rr = t >> 3;
        // Q rows via cp.async
        {
            int row = rr;
            int qx = row >> 3, qy = row & 7;
            size_t pix = (size_t)(bi * 4096 + (bh * 8 + qx) * 64 + bw * 8 + qy) * QKVC + hco;
            cp16(qB + ((uint32_t)(row * 9 + chunk) << 4), g_qh + pix + chunk * 8);
            row = rr + 32;
            qx = row >> 3; qy = row & 7;
            pix = (size_t)(bi * 4096 + (bh * 8 + qx) * 64 + bw * 8 + qy) * QKVC + hco;
            cp16(qB + ((uint32_t)(row * 9 + chunk) << 4), g_qh + pix + chunk * 8);
        }
        // K rows via cp.async with zero-fill for masked positions
#pragma unroll
        for (int p = 0; p < 8; p++) {
            int row = p * 32 + rr;
            int ki = row >> 4, kj = row & 15;
            int gh = bh * 8 - 4 + ki, gw = bw * 8 - 4 + kj;
            bool valid = ((unsigned)gh < 64u) && ((unsigned)gw < 64u);
            size_t pix = (size_t)(valid ? bi * 4096 + gh * 64 + gw : bi * 4096) * QKVC
                       + 256 + hco + chunk * 8;
            cp16z(kB + ((uint32_t)(row * 9 + chunk) << 4), g_qh + pix, valid ? 16u : 0u);
        }
        CP_COMMIT();
        // rel tables: zero pad region, then fill fp16
        for (int idx = t; idx < 1152; idx += 256) {
            ((uint32_t*)(smc + AT_RELH))[idx] = 0;
            ((uint32_t*)(smc + AT_RELW))[idx] = 0;
        }
        __syncthreads();
        for (int idx = t; idx < 1984; idx += 256) {
            int r = idx >> 6, dd = idx & 63;
            ((__half*)(smc + AT_RELH))[r * 72 + dd] = __float2half_rn(relh[idx]);
            ((__half*)(smc + AT_RELW))[r * 72 + dd] = __float2half_rn(relw[idx]);
        }
        CP_WAIT0();
    }
    __syncthreads();

    // ---- rel logits via MMA: wn==0 -> Gw, wn==1 -> Gh ----
    {
        float racc[4][4];
#pragma unroll
        for (int a = 0; a < 4; a++)
#pragma unroll
            for (int b = 0; b < 4; b++) racc[a][b] = 0.f;
        uint32_t relB = sb + (wn ? AT_RELH : AT_RELW);
#pragma unroll
        for (int kt = 0; kt < 4; kt++) {
            uint32_t ah[4];
            ldm4(ah, qB + (((wm * 16 + (lane & 15)) * 72 + kt * 16 + ((lane >> 4) << 3)) << 1));
#pragma unroll
            for (int nb = 0; nb < 2; nb++) {
                uint32_t bh4[4];
                ldm4(bh4, relB + (((nb * 16 + ((lane >> 4) << 3) + (lane & 7)) * 72
                                   + kt * 16 + (((lane >> 3) & 1) << 3)) << 1));
                mma_f16(racc[nb * 2],     ah, bh4[0], bh4[1]);
                mma_f16(racc[nb * 2 + 1], ah, bh4[2], bh4[3]);
            }
        }
        float* G = (float*)(smc + (wn ? AT_GH : AT_GW));
        int g2 = lane >> 2, tt = lane & 3;
#pragma unroll
        for (int j = 0; j < 4; j++)
#pragma unroll
            for (int e = 0; e < 4; e++) {
                int row = wm * 16 + g2 + ((e >= 2) ? 8 : 0);
                int col = j * 8 + 2 * tt + (e & 1);
                G[row * 33 + col] = racc[j][e];
            }
    }

    // ---- QK^T ----
    float s[16][4];
#pragma unroll
    for (int a = 0; a < 16; a++)
#pragma unroll
        for (int b = 0; b < 4; b++) s[a][b] = 0.f;
#pragma unroll
    for (int kt = 0; kt < 4; kt++) {
        uint32_t ah[4];
        ldm4(ah, qB + (((wm * 16 + (lane & 15)) * 72 + kt * 16 + ((lane >> 4) << 3)) << 1));
#pragma unroll
        for (int nb = 0; nb < 8; nb++) {
            uint32_t boff = (((wn * 128 + nb * 16 + ((lane >> 4) << 3) + (lane & 7)) * 72
                             + kt * 16 + (((lane >> 3) & 1) << 3)) << 1);
            uint32_t bh4[4];
            ldm4(bh4, kB + boff);
            mma_f16(s[nb * 2],     ah, bh4[0], bh4[1]);
            mma_f16(s[nb * 2 + 1], ah, bh4[2], bh4[3]);
        }
    }
    __syncthreads();

    // ---- prefetch V into K buffer ----
    {
        int chunk = t & 7, rr = t >> 3;
#pragma unroll
        for (int p = 0; p < 8; p++) {
            int row = p * 32 + rr;
            int ki = row >> 4, kj = row & 15;
            int gh = bh * 8 - 4 + ki, gw = bw * 8 - 4 + kj;
            bool valid = ((unsigned)gh < 64u) && ((unsigned)gw < 64u);
            size_t pix = (size_t)(valid ? bi * 4096 + gh * 64 + gw : bi * 4096) * QKVC
                       + 512 + hco + chunk * 8;
            cp16z(kB + ((uint32_t)(row * 9 + chunk) << 4), g_qh + pix, valid ? 16u : 0u);
        }
        CP_COMMIT();
    }

    // ---- fixup: rel logits + mask ----
    {
        const float* Gw = (const float*)(smc + AT_GW);
        const float* Gh = (const float*)(smc + AT_GH);
        int g = lane >> 2, tt = lane & 3;
#pragma unroll
        for (int nt = 0; nt < 16; nt++) {
            int jbase = wn * 128 + nt * 8 + 2 * tt;
#pragma unroll
            for (int e = 0; e < 4; e++) {
                int row = wm * 16 + g + ((e >= 2) ? 8 : 0);
                int jj = jbase + (e & 1);
                int ki = jj >> 4, kj = jj & 15;
                int gh = bh * 8 - 4 + ki, gw = bw * 8 - 4 + kj;
                if (((unsigned)gh >= 64u) || ((unsigned)gw >= 64u))
                    s[nt][e] = -3.0e38f;
                else
                    s[nt][e] += Gw[row * 33 + kj - (row & 7) + 15]
                              + Gh[row * 33 + ki - (row >> 3) + 15];
            }
        }
    }

    float* rmx  = (float*)(smc + AT_RMX);
    float* rsum = (float*)(smc + AT_RSUM);
    int gg = lane >> 2;
    int rA = wm * 16 + gg, rB = rA + 8;
    {
        float mA = -3.4e38f, mB = -3.4e38f;
#pragma unroll
        for (int nt = 0; nt < 16; nt++) {
            mA = fmaxf(mA, fmaxf(s[nt][0], s[nt][1]));
            mB = fmaxf(mB, fmaxf(s[nt][2], s[nt][3]));
        }
        mA = fmaxf(mA, __shfl_xor_sync(0xffffffffu, mA, 1));
        mA = fmaxf(mA, __shfl_xor_sync(0xffffffffu, mA, 2));
        mB = fmaxf(mB, __shfl_xor_sync(0xffffffffu, mB, 1));
        mB = fmaxf(mB, __shfl_xor_sync(0xffffffffu, mB, 2));
        if ((lane & 3) == 0) { rmx[wn * 64 + rA] = mA; rmx[wn * 64 + rB] = mB; }
    }
    __syncthreads();
    {
        float mA = fmaxf(rmx[rA], rmx[64 + rA]);
        float mB = fmaxf(rmx[rB], rmx[64 + rB]);
        float sA = 0.f, sB = 0.f;
#pragma unroll
        for (int nt = 0; nt < 16; nt++) {
            s[nt][0] = __expf(s[nt][0] - mA); sA += s[nt][0];
            s[nt][1] = __expf(s[nt][1] - mA); sA += s[nt][1];
            s[nt][2] = __expf(s[nt][2] - mB); sB += s[nt][2];
            s[nt][3] = __expf(s[nt][3] - mB); sB += s[nt][3];
        }
        sA += __shfl_xor_sync(0xffffffffu, sA, 1);
        sA += __shfl_xor_sync(0xffffffffu, sA, 2);
        sB += __shfl_xor_sync(0xffffffffu, sB, 1);
        sB += __shfl_xor_sync(0xffffffffu, sB, 2);
        if ((lane & 3) == 0) { rsum[wn * 64 + rA] = sA; rsum[wn * 64 + rB] = sB; }
    }
    __syncthreads();
    {
        float invA = 1.0f / (rsum[rA] + rsum[64 + rA]);
        float invB = 1.0f / (rsum[rB] + rsum[64 + rB]);
#pragma unroll
        for (int nt = 0; nt < 16; nt++) {
            __half h0 = __float2half_rn(s[nt][0] * invA);
            __half h1 = __float2half_rn(s[nt][1] * invA);
            __half h2 = __float2half_rn(s[nt][2] * invB);
            __half h3 = __float2half_rn(s[nt][3] * invB);
            s[nt][0] = __uint_as_float(packh(h0, h1));
            s[nt][1] = __uint_as_float(packh(h2, h3));
        }
    }
    CP_WAIT0();
    __syncthreads();

    // ---- AV ----
    float avc[8][4];
#pragma unroll
    for (int a = 0; a < 8; a++)
#pragma unroll
        for (int b = 0; b < 4; b++) avc[a][b] = 0.f;
#pragma unroll
    for (int kt2 = 0; kt2 < 8; kt2++) {
        uint32_t pa[4] = { __float_as_uint(s[2 * kt2][0]), __float_as_uint(s[2 * kt2][1]),
                           __float_as_uint(s[2 * kt2 + 1][0]), __float_as_uint(s[2 * kt2 + 1][1]) };
#pragma unroll
        for (int nb = 0; nb < 4; nb++) {
            uint32_t off = (((wn * 128 + kt2 * 16 + ((lane >> 3) & 1) * 8 + (lane & 7)) * 72
                            + nb * 16 + ((lane >> 4) << 3)) << 1);
            uint32_t vh4[4];
            ldm4t(vh4, kB + off);
            mma_f16(avc[nb * 2],     pa, vh4[0], vh4[1]);
            mma_f16(avc[nb * 2 + 1], pa, vh4[2], vh4[3]);
        }
    }

    // dual-buffer reduction: wn==0 -> Red1 (overlays sK), wn==1 -> Red2
    float* Red1 = (float*)(smc + AT_SK);
    float* Red2 = (float*)(smc + AT_RED2);
    __syncthreads();
    {
        float* Rd = wn ? Red2 : Red1;
#pragma unroll
        for (int nf = 0; nf < 8; nf++)
#pragma unroll
            for (int e = 0; e < 4; e++) {
                int row = wm * 16 + gg + ((e >= 2) ? 8 : 0);
                int col = nf * 8 + 2 * (lane & 3) + (e & 1);
                Rd[row * 68 + col] = avc[nf][e];
            }
    }
    __syncthreads();

    {
        int qi = t >> 2, c0 = (t & 3) * 16;
        int qx = qi >> 3, qy = qi & 7;
        size_t base = (size_t)(bi * 4096 + (bh * 8 + qx) * 64 + bw * 8 + qy) * 256 + hco + c0;
        unsigned short hs[16];
#pragma unroll
        for (int u = 0; u < 16; u++)
            hs[u] = __half_as_ushort(__float2half_rn(Red1[qi * 68 + c0 + u]
                                                   + Red2[qi * 68 + c0 + u]));
        *(uint4*)&g_bh[base]     = *(uint4*)&hs[0];
        *(uint4*)&g_bh[base + 8] = *(uint4*)&hs[8];
    }
}

// ---------------------------------------------------------------------------
// K3: output GEMM + PixelShuffle. fp16 single-term, 4-stage cg ring, unrolled.
// ---------------------------------------------------------------------------
#define KO_BUF  20480
#define KO_SMEM (KO_BUF * 4)

__global__ void __launch_bounds__(256, 2) k_out_tc(float* __restrict__ out)
{
    extern __shared__ char osm[];
    uint32_t base = smem_u32(osm);
    int tid = threadIdx.x, lane = tid & 31, wrp = tid >> 5;
    int wm = wrp >> 1, wn = wrp & 1;
    int mt = blockIdx.y, n0 = blockIdx.x << 7;
    int m0 = mt << 7;

    float acc[2][8][4];
#pragma unroll
    for (int a = 0; a < 2; a++)
#pragma unroll
        for (int b = 0; b < 8; b++)
#pragma unroll
            for (int c = 0; c < 4; c++) acc[a][b][c] = 0.f;

    int ar = tid >> 1, ac = (tid & 1) << 4;

    auto issue = [&](int s, int buf) {
        int kk = s << 5;
        uint32_t qa = base + buf * KO_BUF;
        const __half* A = g_wfh + (size_t)(m0 + ar) * 256 + kk + ac;
        uint32_t da = qa + ((ar * 40 + ac) << 1);
        cp16(da, A); cp16(da + 16, A + 8);
        const __half* B = g_bh + (size_t)(n0 + ar) * 256 + kk + ac;
        uint32_t db = qa + 10240 + ((ar * 40 + ac) << 1);
        cp16(db, B); cp16(db + 16, B + 8);
    };
    auto compute = [&](int buf) {
        uint32_t qa = base + buf * KO_BUF;
        uint32_t ab = qa, bb = qa + 10240;
#pragma unroll
        for (int kh = 0; kh < 32; kh += 16) {
            uint32_t ah[2][4];
#pragma unroll
            for (int mf = 0; mf < 2; mf++)
                ldm4(ah[mf], ab + (((wm * 32 + mf * 16 + (lane & 15)) * 40
                                   + kh + ((lane >> 4) << 3)) << 1));
#pragma unroll
            for (int nb = 0; nb < 4; nb++) {
                uint32_t bh4[4];
                ldm4(bh4, bb + (((wn * 64 + nb * 16 + ((lane >> 4) << 3) + (lane & 7)) * 40
                                 + kh + (((lane >> 3) & 1) << 3)) << 1));
#pragma unroll
                for (int mf = 0; mf < 2; mf++) {
                    mma_f16(acc[mf][nb * 2],     ah[mf], bh4[0], bh4[1]);
                    mma_f16(acc[mf][nb * 2 + 1], ah[mf], bh4[2], bh4[3]);
                }
            }
        }
    };

    issue(0, 0); CP_COMMIT();
    issue(1, 1); CP_COMMIT();
    issue(2, 2); CP_COMMIT();
#pragma unroll
    for (int s = 0; s < 8; s++) {
        if (s < 6) CP_WAIT2();
        else if (s == 6) CP_WAIT1();
        else CP_WAIT0();
        __syncthreads();
        if (s + 3 < 8) { issue(s + 3, (s + 3) & 3); CP_COMMIT(); }
        compute(s & 3);
    }

    int g = lane >> 2, q = lane & 3;
    int h0 = (n0 & 4095) >> 6, bimg = n0 >> 12;
    int hrow = h0 + wn;
#pragma unroll
    for (int mf = 0; mf < 2; mf++) {
#pragma unroll
        for (int which = 0; which < 2; which++) {
            int mm = m0 + wm * 32 + mf * 16 + g + which * 8;
            float bias = g_bf[mm];
            int cch = mm >> 2, r = (mm >> 1) & 1, s2 = mm & 1;
            float* rowp = out + ((size_t)(bimg * 256 + cch) * 128 + 2 * hrow + r) * 128 + s2;
#pragma unroll
            for (int nf = 0; nf < 8; nf++) {
                int w0 = nf * 8 + 2 * q;
                rowp[2 * w0]     = acc[mf][nf][which * 2 + 0] + bias;
                rowp[2 * w0 + 2] = acc[mf][nf][which * 2 + 1] + bias;
            }
        }
    }
}

// ---------------------------------------------------------------------------
extern "C" void kernel_launch(void* const* d_in, const int* in_sizes, int n_in,
                              void* d_out, int out_size)
{
    const float* x    = (const float*)d_in[0];
    const float* wq   = (const float*)d_in[1];
    const float* wkv  = (const float*)d_in[2];
    const float* wo   = (const float*)d_in[3];
    const float* bo   = (const float*)d_in[4];
    const float* relh = (const float*)d_in[5];
    const float* relw = (const float*)d_in[6];
    const float* wc   = (const float*)d_in[7];
    const float* bc   = (const float*)d_in[8];
    float* out = (float*)d_out;

    cudaFuncSetAttribute(k_qkv_tc,  cudaFuncAttributeMaxDynamicSharedMemorySize, QK_SMEM);
    cudaFuncSetAttribute(k_attn_tc, cudaFuncAttributeMaxDynamicSharedMemorySize, AT_SMEM);
    cudaFuncSetAttribute(k_out_tc,  cudaFuncAttributeMaxDynamicSharedMemorySize, KO_SMEM);

    k_fuse<<<256, 256>>>(wo, bo, wc, bc);
    k_splitw<<<768, 256>>>(wq, wkv);
    k_splitx<<<8192, 256>>>(x);
    k_qkv_tc<<<dim3(256, 6), 256, QK_SMEM>>>();
    k_attn_tc<<<dim3(512, 4), 256, AT_SMEM>>>(relh, relw);
    k_out_tc<<<dim3(256, 8), 256, KO_SMEM>>>(out);
}